// round 4
// baseline (speedup 1.0000x reference)
#include <cuda_runtime.h>

// Problem constants
#define Bdim   4
#define Tdim   4
#define Cdim   32
#define Ndim   16384
#define Fdim   64
#define Kdim   9
#define PADl   4
#define TILE_N 128
#define CK     (Cdim * Kdim)   // 288

// Pre-transposed weights: [t][ck][f], ck = c*K + k (matches einsum 'tfck' flatten)
__device__ float g_wT[Tdim * CK * Fdim];   // 73728 floats = 288 KB

__global__ void transpose_w_kernel(const float* __restrict__ w) {
    int idx = blockIdx.x * blockDim.x + threadIdx.x;
    if (idx >= Tdim * Fdim * CK) return;
    int t  = idx / (Fdim * CK);
    int r  = idx - t * (Fdim * CK);
    int f  = r / CK;
    int ck = r - f * CK;
    g_wT[(t * CK + ck) * Fdim + f] = w[idx];
}

__global__ __launch_bounds__(128, 4)
void sepconv_kernel(const float* __restrict__ x,
                    const float* __restrict__ coords,
                    const unsigned* __restrict__ sigma_p,
                    float* __restrict__ out)
{
    __shared__ float xs[Cdim][TILE_N + 8];   // x tile with halo     (17408 B)
    __shared__ float cs[3][TILE_N + 8];      // coords tile w/ halo  ( 1632 B)
    __shared__ float ws[Kdim][TILE_N];       // distance weights     ( 4608 B)
    __shared__ float wsh[32][Fdim];          // weight chunk [j][f]  ( 8192 B)
    __shared__ float bs[32][TILE_N];         // Bmat chunk  [j][n]   (16384 B)
    // total 48224 B static shared -> 4 CTAs/SM

    const int tid = threadIdx.x;             // 0..127
    const int bt  = blockIdx.y;              // b*T + t
    const int t   = bt & (Tdim - 1);
    const int n0  = blockIdx.x * TILE_N;

    // sigma: tolerate int32 or float32 encoding
    unsigned sb = *sigma_p;
    float sigma = (sb < 0x01000000u) ? (float)(int)sb : __uint_as_float(sb);
    float inv_sigma = 1.0f / sigma;

    // ---- stage x tile (with halo, zero-padded) ----
    const float* xb = x + (size_t)bt * Cdim * Ndim;
    #pragma unroll 4
    for (int idx = tid; idx < Cdim * (TILE_N + 8); idx += 128) {
        int c = idx / (TILE_N + 8);
        int i = idx - c * (TILE_N + 8);
        int m = n0 + i - PADl;
        xs[c][i] = (m >= 0 && m < Ndim) ? xb[c * Ndim + m] : 0.0f;
    }
    // ---- stage coords tile ----
    const float* cb = coords + (size_t)bt * 3 * Ndim;
    for (int idx = tid; idx < 3 * (TILE_N + 8); idx += 128) {
        int d = idx / (TILE_N + 8);
        int i = idx - d * (TILE_N + 8);
        int m = n0 + i - PADl;
        cs[d][i] = (m >= 0 && m < Ndim) ? cb[d * Ndim + m] : 0.0f;
    }
    __syncthreads();

    // ---- distance weights ws[k][n] ----
    #pragma unroll
    for (int it = 0; it < 9; it++) {
        int idx = it * 128 + tid;
        int k = idx >> 7;          // TILE_N = 128
        int n = idx & 127;
        float dx = cs[0][n + k] - cs[0][n + PADl];
        float dy = cs[1][n + k] - cs[1][n + PADl];
        float dz = cs[2][n + k] - cs[2][n + PADl];
        float d2 = dx * dx + dy * dy + dz * dz;
        float w  = 1.0f - sqrtf(d2) * inv_sigma;
        ws[k][n] = fmaxf(w, 0.0f);
    }
    __syncthreads();

    // ---- register-tiled GEMM: [64 f] x [288 ck] x [128 n], 8f x 8n per thread ----
    const int fi = tid >> 4;         // 0..7
    const int ni = tid & 15;         // 0..15
    const int f0 = fi * 8;
    const int nl = ni * 8;

    float acc[8][8];
    #pragma unroll
    for (int a = 0; a < 8; a++)
        #pragma unroll
        for (int b = 0; b < 8; b++) acc[a][b] = 0.0f;

    const float* wtb = g_wT + (size_t)t * CK * Fdim;

    for (int ch = 0; ch < 9; ch++) {
        // fill weight chunk wsh[j][f]  (coalesced gmem, conflict-free STS)
        #pragma unroll
        for (int it = 0; it < 16; it++) {
            int idx = it * 128 + tid;          // j = idx>>6, f = idx&63 contiguous
            wsh[idx >> 6][idx & 63] = wtb[ch * 32 * Fdim + idx];
        }
        // build Bmat chunk bs[j][n] = x[c][n+k] * ws[k][n]
        #pragma unroll
        for (int it = 0; it < 32; it++) {
            int idx = it * 128 + tid;
            int j = idx >> 7, n = idx & 127;
            int ck = ch * 32 + j;
            int c  = ck / 9;
            int k  = ck - c * 9;
            bs[j][n] = xs[c][n + k] * ws[k][n];
        }
        __syncthreads();

        #pragma unroll 8
        for (int j = 0; j < 32; j++) {
            float4 a0 = *(const float4*)&wsh[j][f0];
            float4 a1 = *(const float4*)&wsh[j][f0 + 4];
            float4 b0 = *(const float4*)&bs[j][nl];
            float4 b1 = *(const float4*)&bs[j][nl + 4];
            float av[8] = {a0.x, a0.y, a0.z, a0.w, a1.x, a1.y, a1.z, a1.w};
            float bv[8] = {b0.x, b0.y, b0.z, b0.w, b1.x, b1.y, b1.z, b1.w};
            #pragma unroll
            for (int ff = 0; ff < 8; ff++)
                #pragma unroll
                for (int nn = 0; nn < 8; nn++)
                    acc[ff][nn] = fmaf(av[ff], bv[nn], acc[ff][nn]);
        }
        __syncthreads();
    }

    // ---- epilogue: vectorized stores ----
    float* ob = out + (size_t)bt * Fdim * Ndim;
    #pragma unroll
    for (int ff = 0; ff < 8; ff++) {
        float* p = ob + (size_t)(f0 + ff) * Ndim + n0 + nl;
        *(float4*)p       = make_float4(acc[ff][0], acc[ff][1], acc[ff][2], acc[ff][3]);
        *(float4*)(p + 4) = make_float4(acc[ff][4], acc[ff][5], acc[ff][6], acc[ff][7]);
    }
}

extern "C" void kernel_launch(void* const* d_in, const int* in_sizes, int n_in,
                              void* d_out, int out_size)
{
    const float*    x      = (const float*)d_in[0];
    const float*    coords = (const float*)d_in[1];
    const float*    w      = (const float*)d_in[2];
    const unsigned* sigma  = (const unsigned*)d_in[3];
    float*          out    = (float*)d_out;

    transpose_w_kernel<<<(Tdim * Fdim * CK + 255) / 256, 256>>>(w);

    dim3 grid(Ndim / TILE_N, Bdim * Tdim);
    sepconv_kernel<<<grid, 128>>>(x, coords, sigma, out);
}

// round 6
// speedup vs baseline: 2.1340x; 2.1340x over previous
#include <cuda_runtime.h>
#include <cuda_bf16.h>
#include <cstdint>

#define Bdim 4
#define Tdim 4
#define Cdim 32
#define Ndim 16384
#define Fdim 64
#define Kdim 9
#define CK   288
#define KP   864            // 3*CK (3-product expansion)
#define NCH  6
#define CHK  144            // k' per chunk (48 logical ck), 9 k16-steps
#define TILE_N 128

// smem layout (bytes)
#define PA 304              // A chunk pitch (152 bf16), 16B aligned, conflict-free
#define PB 272              // B chunk pitch (136 bf16), 16B aligned, conflict-free
#define OFF_XS 0            // float [32][136] = 17408
#define OFF_WS 17408        // float [9][128]  =  4608
#define OFF_A  22016        // 64 rows * 304   = 19456
#define OFF_B  41472        // 144 rows * 272  = 39168
#define SMEM_TOTAL 80640

// Pre-split A': [t][f=64][k'=864] bf16, k' = 3*ck + r, triplet (a_hi, a_hi, a_lo)
__device__ __align__(16) __nv_bfloat16 g_wA[Tdim * Fdim * KP];   // 442 KB

__global__ void prep_w(const float* __restrict__ w) {
    int idx = blockIdx.x * 256 + threadIdx.x;
    if (idx >= Tdim * Fdim * KP) return;
    int kp = idx % KP;
    int fm = idx / KP;
    int f  = fm & 63;
    int t  = fm >> 6;
    int ck = kp / 3, r = kp - 3 * ck;
    int c  = ck / 9, kk = ck - 9 * c;
    float val = w[((t * Fdim + f) * Cdim + c) * Kdim + kk];
    __nv_bfloat16 hi = __float2bfloat16_rn(val);
    __nv_bfloat16 e  = (r == 2) ? __float2bfloat16_rn(val - __bfloat162float(hi)) : hi;
    g_wA[idx] = e;
}

__device__ __forceinline__ uint32_t smem_u32(const void* p) {
    uint32_t a;
    asm("{ .reg .u64 t; cvta.to.shared.u64 t, %1; cvt.u32.u64 %0, t; }" : "=r"(a) : "l"(p));
    return a;
}

#define LDSM_X4(r0,r1,r2,r3, addr) \
    asm volatile("ldmatrix.sync.aligned.m8n8.x4.shared.b16 {%0,%1,%2,%3}, [%4];" \
        : "=r"(r0),"=r"(r1),"=r"(r2),"=r"(r3) : "r"(addr))

#define LDSM_X4T(r0,r1,r2,r3, addr) \
    asm volatile("ldmatrix.sync.aligned.m8n8.x4.trans.shared.b16 {%0,%1,%2,%3}, [%4];" \
        : "=r"(r0),"=r"(r1),"=r"(r2),"=r"(r3) : "r"(addr))

#define MMA16816(c0,c1,c2,c3, a0,a1,a2,a3, b0,b1) \
    asm volatile("mma.sync.aligned.m16n8k16.row.col.f32.bf16.bf16.f32 " \
        "{%0,%1,%2,%3},{%4,%5,%6,%7},{%8,%9},{%0,%1,%2,%3};" \
        : "+f"(c0),"+f"(c1),"+f"(c2),"+f"(c3) \
        : "r"(a0),"r"(a1),"r"(a2),"r"(a3),"r"(b0),"r"(b1))

__global__ __launch_bounds__(256, 2)
void sepconv_mma_kernel(const float* __restrict__ x,
                        const float* __restrict__ coords,
                        const unsigned* __restrict__ sigma_p,
                        float* __restrict__ out)
{
    extern __shared__ __align__(16) unsigned char sm[];
    float* xs = (float*)(sm + OFF_XS);     // [32][136], halo
    float* ws = (float*)(sm + OFF_WS);     // [9][128]

    const int tid  = threadIdx.x;
    const int warp = tid >> 5;
    const int lane = tid & 31;
    const int bt   = blockIdx.y;
    const int t    = bt & (Tdim - 1);
    const int n0   = blockIdx.x * TILE_N;

    unsigned sb = *sigma_p;
    float sigma = (sb < 0x01000000u) ? (float)(int)sb : __uint_as_float(sb);
    float inv_sigma = 1.0f / sigma;

    // ---- stage x tile (halo, zero-padded) ----
    const float* xb = x + (size_t)bt * Cdim * Ndim;
    for (int idx = tid; idx < Cdim * 136; idx += 256) {
        int c = idx / 136, i = idx - c * 136;
        int m = n0 + i - 4;
        xs[idx] = (m >= 0 && m < Ndim) ? xb[c * Ndim + m] : 0.0f;
    }
    // ---- distance weights ws[k][n] ----
    const float* cb = coords + (size_t)bt * 3 * Ndim;
    for (int idx = tid; idx < Kdim * TILE_N; idx += 256) {
        int k = idx >> 7, n = idx & 127;
        int mc = n0 + n, mt2 = mc + k - 4;
        float cx = 0.f, cy = 0.f, cz = 0.f;
        if (mt2 >= 0 && mt2 < Ndim) { cx = cb[mt2]; cy = cb[Ndim + mt2]; cz = cb[2 * Ndim + mt2]; }
        float dx = cx - cb[mc], dy = cy - cb[Ndim + mc], dz = cz - cb[2 * Ndim + mc];
        float d2 = dx * dx + dy * dy + dz * dz;
        ws[k * 128 + n] = fmaxf(1.0f - sqrtf(d2) * inv_sigma, 0.0f);
    }
    __syncthreads();

    // warp tiling: 4 m16-tiles x 2 n64-halves
    const int mt = warp & 3;        // m-tile (16 f-rows)
    const int nh = warp >> 2;       // n-half (64 cols)

    float acc[8][4];
    #pragma unroll
    for (int j = 0; j < 8; j++)
        #pragma unroll
        for (int q = 0; q < 4; q++) acc[j][q] = 0.0f;

    const uint32_t As = smem_u32(sm + OFF_A);
    const uint32_t Bs = smem_u32(sm + OFF_B);
    const int g = lane >> 3, r = lane & 7;

    // per-lane LDSM base addresses
    const uint32_t a_lane = As + (uint32_t)((mt * 16 + (g & 1) * 8 + r) * PA + (g >> 1) * 16);
    const uint32_t b_lane = Bs + (uint32_t)(((g & 1) * 8 + r) * PB + (nh * 64 + (g >> 1) * 8) * 2);

    for (int ch = 0; ch < NCH; ch++) {
        // ---- load A' chunk: 64 rows x 144 bf16 (288B = 18 uint4 per row) ----
        {
            const uint4* src = (const uint4*)(g_wA + ((size_t)t * Fdim) * KP + ch * CHK);
            #pragma unroll
            for (int it = 0; it < 5; it++) {
                int idx = it * 256 + tid;
                if (idx < 64 * 18) {
                    int row = idx / 18, col = idx - row * 18;
                    *(uint4*)(sm + OFF_A + row * PA + col * 16) =
                        src[(size_t)row * (KP / 8) + col];
                }
            }
        }
        // ---- build B' chunk: rows 3cc+{0,1,2} = (bh, bl, bh), cols n ----
        {
            int n2  = tid & 63;          // n pair: n = 2*n2
            int ckr = tid >> 6;          // 0..3
            unsigned* b32 = (unsigned*)(sm + OFF_B);
            #pragma unroll
            for (int cc = 0; cc < 48; cc += 4) {
                int ccl = cc + ckr;
                int ck = ch * 48 + ccl;
                int c = ck / 9, k = ck - 9 * c;
                int nn = 2 * n2;
                float v0 = xs[c * 136 + nn + k]     * ws[k * 128 + nn];
                float v1 = xs[c * 136 + nn + 1 + k] * ws[k * 128 + nn + 1];
                __nv_bfloat162 h2 = __floats2bfloat162_rn(v0, v1);
                float r0 = v0 - __bfloat162float(__low2bfloat16(h2));
                float r1 = v1 - __bfloat162float(__high2bfloat16(h2));
                __nv_bfloat162 l2 = __floats2bfloat162_rn(r0, r1);
                unsigned hh = *(unsigned*)&h2;
                unsigned ll = *(unsigned*)&l2;
                b32[(3 * ccl + 0) * (PB / 4) + n2] = hh;
                b32[(3 * ccl + 1) * (PB / 4) + n2] = ll;
                b32[(3 * ccl + 2) * (PB / 4) + n2] = hh;
            }
        }
        __syncthreads();

        // ---- MMA phase: 9 k16-steps ----
        #pragma unroll
        for (int ks = 0; ks < 9; ks++) {
            uint32_t a0, a1, a2, a3;
            LDSM_X4(a0, a1, a2, a3, a_lane + ks * 32);
            #pragma unroll
            for (int bp = 0; bp < 4; bp++) {
                uint32_t b0, b1, b2, b3;
                LDSM_X4T(b0, b1, b2, b3, b_lane + ks * 16 * PB + bp * 32);
                MMA16816(acc[bp*2][0],   acc[bp*2][1],   acc[bp*2][2],   acc[bp*2][3],
                         a0, a1, a2, a3, b0, b1);
                MMA16816(acc[bp*2+1][0], acc[bp*2+1][1], acc[bp*2+1][2], acc[bp*2+1][3],
                         a0, a1, a2, a3, b2, b3);
            }
        }
        __syncthreads();
    }

    // ---- epilogue: register fragments -> gmem ----
    float* ob = out + (size_t)bt * Fdim * Ndim;
    const int drow = lane >> 2;
    const int dcol = (lane & 3) * 2;
    #pragma unroll
    for (int j = 0; j < 8; j++) {
        int f  = mt * 16 + drow;
        int nc = n0 + nh * 64 + j * 8 + dcol;
        *(float2*)&ob[(size_t)f * Ndim + nc]       = make_float2(acc[j][0], acc[j][1]);
        *(float2*)&ob[(size_t)(f + 8) * Ndim + nc] = make_float2(acc[j][2], acc[j][3]);
    }
}

extern "C" void kernel_launch(void* const* d_in, const int* in_sizes, int n_in,
                              void* d_out, int out_size)
{
    const float*    x      = (const float*)d_in[0];
    const float*    coords = (const float*)d_in[1];
    const float*    w      = (const float*)d_in[2];
    const unsigned* sigma  = (const unsigned*)d_in[3];
    float*          out    = (float*)d_out;

    static int smem_set = 0;
    if (!smem_set) {
        cudaFuncSetAttribute(sepconv_mma_kernel,
                             cudaFuncAttributeMaxDynamicSharedMemorySize, SMEM_TOTAL);
        smem_set = 1;
    }

    prep_w<<<(Tdim * Fdim * KP + 255) / 256, 256>>>(w);

    dim3 grid(Ndim / TILE_N, Bdim * Tdim);
    sepconv_mma_kernel<<<grid, 256, SMEM_TOTAL>>>(x, coords, sigma, out);
}

// round 7
// speedup vs baseline: 2.2199x; 1.0403x over previous
#include <cuda_runtime.h>
#include <cuda_bf16.h>
#include <cstdint>

#define Bdim 4
#define Tdim 4
#define Cdim 32
#define Ndim 16384
#define Fdim 64
#define Kdim 9
#define CK   288
#define NCH  6
#define CHK  48             // logical k per chunk, 3 k16-steps
#define TILE_N 128

// smem layout (bytes)
#define PA 112              // A row: 48 bf16 = 96B + 16 pad (conflict-free LDSM)
#define PB 272              // B row: 128 bf16 = 256B + 16 pad (conflict-free trans LDSM)
#define ASZ (64 * PA)       // 7168 per A buffer
#define BSZ (CHK * PB)      // 13056 per B buffer
#define OFF_XS 0            // float [32][136] = 17408
#define OFF_WS 17408        // float [9][128]  =  4608
#define OFF_A  22016        // 4 bufs (parity x hi/lo) * 7168  = 28672
#define OFF_B  50688        // 4 bufs (parity x hi/lo) * 13056 = 52224
#define SMEM_TOTAL 102912

// Pre-split A: [h][t][f][ck] bf16 (h=0 hi, h=1 lo)
__device__ __align__(16) __nv_bfloat16 g_wA[2][Tdim * Fdim * CK];

__global__ void prep_w(const float* __restrict__ w) {
    int idx = blockIdx.x * 256 + threadIdx.x;
    if (idx >= Tdim * Fdim * CK) return;
    int ck = idx % CK;
    int fm = idx / CK;
    int f  = fm & 63;
    int t  = fm >> 6;
    int c  = ck / 9, kk = ck - 9 * c;
    float val = w[((t * Fdim + f) * Cdim + c) * Kdim + kk];
    __nv_bfloat16 hi = __float2bfloat16_rn(val);
    g_wA[0][idx] = hi;
    g_wA[1][idx] = __float2bfloat16_rn(val - __bfloat162float(hi));
}

__device__ __forceinline__ uint32_t smem_u32(const void* p) {
    uint32_t a;
    asm("{ .reg .u64 t; cvta.to.shared.u64 t, %1; cvt.u32.u64 %0, t; }" : "=r"(a) : "l"(p));
    return a;
}

#define LDSM_X4(r0,r1,r2,r3, addr) \
    asm volatile("ldmatrix.sync.aligned.m8n8.x4.shared.b16 {%0,%1,%2,%3}, [%4];" \
        : "=r"(r0),"=r"(r1),"=r"(r2),"=r"(r3) : "r"(addr))

#define LDSM_X4T(r0,r1,r2,r3, addr) \
    asm volatile("ldmatrix.sync.aligned.m8n8.x4.trans.shared.b16 {%0,%1,%2,%3}, [%4];" \
        : "=r"(r0),"=r"(r1),"=r"(r2),"=r"(r3) : "r"(addr))

#define MMA16816(c, a0,a1,a2,a3, b0,b1) \
    asm volatile("mma.sync.aligned.m16n8k16.row.col.f32.bf16.bf16.f32 " \
        "{%0,%1,%2,%3},{%4,%5,%6,%7},{%8,%9},{%0,%1,%2,%3};" \
        : "+f"((c)[0]),"+f"((c)[1]),"+f"((c)[2]),"+f"((c)[3]) \
        : "r"(a0),"r"(a1),"r"(a2),"r"(a3),"r"(b0),"r"(b1))

__global__ __launch_bounds__(256, 2)
void sepconv_mma_kernel(const float* __restrict__ x,
                        const float* __restrict__ coords,
                        const unsigned* __restrict__ sigma_p,
                        float* __restrict__ out)
{
    extern __shared__ __align__(16) unsigned char sm[];
    float* xs = (float*)(sm + OFF_XS);     // [32][136], halo
    float* ws = (float*)(sm + OFF_WS);     // [9][128]

    const int tid  = threadIdx.x;
    const int warp = tid >> 5;
    const int lane = tid & 31;
    const int bt   = blockIdx.y;
    const int t    = bt & (Tdim - 1);
    const int n0   = blockIdx.x * TILE_N;

    unsigned sb = *sigma_p;
    float sigma = (sb < 0x01000000u) ? (float)(int)sb : __uint_as_float(sb);
    float inv_sigma = 1.0f / sigma;

    // ---- stage x tile (halo, zero-padded) ----
    const float* xb = x + (size_t)bt * Cdim * Ndim;
    for (int idx = tid; idx < Cdim * 136; idx += 256) {
        int c = idx / 136, i = idx - c * 136;
        int m = n0 + i - 4;
        xs[idx] = (m >= 0 && m < Ndim) ? xb[c * Ndim + m] : 0.0f;
    }
    // ---- distance weights ws[k][n] ----
    const float* cb = coords + (size_t)bt * 3 * Ndim;
    for (int idx = tid; idx < Kdim * TILE_N; idx += 256) {
        int k = idx >> 7, n = idx & 127;
        int mc = n0 + n, mt2 = mc + k - 4;
        float cx = 0.f, cy = 0.f, cz = 0.f;
        if (mt2 >= 0 && mt2 < Ndim) { cx = cb[mt2]; cy = cb[Ndim + mt2]; cz = cb[2 * Ndim + mt2]; }
        float dx = cx - cb[mc], dy = cy - cb[Ndim + mc], dz = cz - cb[2 * Ndim + mc];
        float d2 = dx * dx + dy * dy + dz * dz;
        ws[k * 128 + n] = fmaxf(1.0f - sqrtf(d2) * inv_sigma, 0.0f);
    }
    __syncthreads();

    // warp tiling: 4 m16-tiles x 2 n64-halves
    const int mt = warp & 3;
    const int nh = warp >> 2;

    float acc[8][4];
    #pragma unroll
    for (int j = 0; j < 8; j++)
        #pragma unroll
        for (int q = 0; q < 4; q++) acc[j][q] = 0.0f;

    const uint32_t smb = smem_u32(sm);
    const int g = lane >> 3, rr = lane & 7;
    const uint32_t a_off = (uint32_t)((mt * 16 + (g & 1) * 8 + rr) * PA + (g >> 1) * 16);
    const uint32_t b_off = (uint32_t)(((g & 1) * 8 + rr) * PB + (nh * 64 + (g >> 1) * 8) * 2);

    // B-build thread mapping
    const int n2  = tid & 63;          // n pair
    const int ckr = tid >> 6;          // 0..3

    for (int ch = 0; ch < NCH; ch++) {
        const int p = ch & 1;

        // ---- load A chunk (hi & lo): 64 rows x 48 bf16 = 6 uint4/row ----
        {
            const uint4* srcs[2] = {
                (const uint4*)g_wA[0] + ((size_t)t * Fdim) * 36 + ch * 6,
                (const uint4*)g_wA[1] + ((size_t)t * Fdim) * 36 + ch * 6 };
            #pragma unroll
            for (int it = 0; it < 3; it++) {
                int idx = it * 256 + tid;          // 0..767
                int h   = idx / 384;
                int rem = idx - h * 384;
                int row = rem / 6, col = rem - row * 6;
                *(uint4*)(sm + OFF_A + (p * 2 + h) * ASZ + row * PA + col * 16) =
                    srcs[h][(size_t)row * 36 + col];
            }
        }
        // ---- build B chunk: hi and lo in separate buffers ----
        {
            unsigned* bh32 = (unsigned*)(sm + OFF_B + (p * 2) * BSZ);
            unsigned* bl32 = (unsigned*)(sm + OFF_B + (p * 2 + 1) * BSZ);
            #pragma unroll
            for (int cc = 0; cc < CHK; cc += 4) {
                int ccl = cc + ckr;
                int ck = ch * CHK + ccl;
                int c = ck / 9, k = ck - 9 * c;
                int nn = 2 * n2;
                float v0 = xs[c * 136 + nn + k]     * ws[k * 128 + nn];
                float v1 = xs[c * 136 + nn + 1 + k] * ws[k * 128 + nn + 1];
                __nv_bfloat162 h2 = __floats2bfloat162_rn(v0, v1);
                float r0 = v0 - __bfloat162float(__low2bfloat16(h2));
                float r1 = v1 - __bfloat162float(__high2bfloat16(h2));
                __nv_bfloat162 l2 = __floats2bfloat162_rn(r0, r1);
                bh32[ccl * (PB / 4) + n2] = *(unsigned*)&h2;
                bl32[ccl * (PB / 4) + n2] = *(unsigned*)&l2;
            }
        }
        __syncthreads();   // single barrier per chunk (double-buffered)

        // ---- MMA phase: 3 k16-steps, 3 products sharing fragments ----
        const uint32_t ah_base = smb + OFF_A + (p * 2) * ASZ + a_off;
        const uint32_t al_base = ah_base + ASZ;
        const uint32_t bh_base = smb + OFF_B + (p * 2) * BSZ + b_off;
        const uint32_t bl_base = bh_base + BSZ;
        #pragma unroll
        for (int ks = 0; ks < 3; ks++) {
            uint32_t ah0, ah1, ah2, ah3, al0, al1, al2, al3;
            LDSM_X4(ah0, ah1, ah2, ah3, ah_base + ks * 32);
            LDSM_X4(al0, al1, al2, al3, al_base + ks * 32);
            #pragma unroll
            for (int bp = 0; bp < 4; bp++) {
                uint32_t bh0, bh1, bh2, bh3, bl0, bl1, bl2, bl3;
                LDSM_X4T(bh0, bh1, bh2, bh3, bh_base + ks * 16 * PB + bp * 32);
                LDSM_X4T(bl0, bl1, bl2, bl3, bl_base + ks * 16 * PB + bp * 32);
                MMA16816(acc[bp*2],   ah0, ah1, ah2, ah3, bh0, bh1);
                MMA16816(acc[bp*2+1], ah0, ah1, ah2, ah3, bh2, bh3);
                MMA16816(acc[bp*2],   ah0, ah1, ah2, ah3, bl0, bl1);
                MMA16816(acc[bp*2+1], ah0, ah1, ah2, ah3, bl2, bl3);
                MMA16816(acc[bp*2],   al0, al1, al2, al3, bh0, bh1);
                MMA16816(acc[bp*2+1], al0, al1, al2, al3, bh2, bh3);
            }
        }
        // no trailing barrier: next build targets the other parity buffers
    }

    // ---- epilogue: register fragments -> gmem ----
    float* ob = out + (size_t)bt * Fdim * Ndim;
    const int drow = lane >> 2;
    const int dcol = (lane & 3) * 2;
    #pragma unroll
    for (int j = 0; j < 8; j++) {
        int f  = mt * 16 + drow;
        int nc = n0 + nh * 64 + j * 8 + dcol;
        *(float2*)&ob[(size_t)f * Ndim + nc]       = make_float2(acc[j][0], acc[j][1]);
        *(float2*)&ob[(size_t)(f + 8) * Ndim + nc] = make_float2(acc[j][2], acc[j][3]);
    }
}

extern "C" void kernel_launch(void* const* d_in, const int* in_sizes, int n_in,
                              void* d_out, int out_size)
{
    const float*    x      = (const float*)d_in[0];
    const float*    coords = (const float*)d_in[1];
    const float*    w      = (const float*)d_in[2];
    const unsigned* sigma  = (const unsigned*)d_in[3];
    float*          out    = (float*)d_out;

    static int smem_set = 0;
    if (!smem_set) {
        cudaFuncSetAttribute(sepconv_mma_kernel,
                             cudaFuncAttributeMaxDynamicSharedMemorySize, SMEM_TOTAL);
        smem_set = 1;
    }

    prep_w<<<(Tdim * Fdim * CK + 255) / 256, 256>>>(w);

    dim3 grid(Ndim / TILE_N, Bdim * Tdim);
    sepconv_mma_kernel<<<grid, 256, SMEM_TOTAL>>>(x, coords, sigma, out);
}

// round 8
// speedup vs baseline: 2.5138x; 1.1324x over previous
#include <cuda_runtime.h>
#include <cuda_bf16.h>
#include <cstdint>

#define Bdim 4
#define Tdim 4
#define Cdim 32
#define Ndim 16384
#define Fdim 64
#define Kdim 9
#define CK   288
#define NCH  6
#define CHK  48             // logical k per chunk, 3 k16-steps
#define TILE_N 128

// smem layout (bytes)
#define PA 112              // A row: 48 bf16 = 96B + 16 pad
#define PB 272              // B row: 128 bf16 = 256B + 16 pad
#define ASZ (64 * PA)       // 7168 per A buffer
#define BSZ (CHK * PB)      // 13056 per B buffer
#define OFF_XS 0            // float [32][136] = 17408
#define OFF_WS 17408        // float [9][128]  =  4608
#define OFF_A  22016        // 4 bufs (parity x hi/lo) * 7168  = 28672
#define OFF_B  50688        // 4 bufs (parity x hi/lo) * 13056 = 52224
#define SMEM_TOTAL 102912

// Pre-split A: [h][t][f][ck] bf16 (h=0 hi, h=1 lo)
__device__ __align__(16) __nv_bfloat16 g_wA[2][Tdim * Fdim * CK];

__global__ void prep_w(const float* __restrict__ w) {
    int idx = blockIdx.x * 256 + threadIdx.x;
    if (idx >= Tdim * Fdim * CK) return;
    int ck = idx % CK;
    int fm = idx / CK;
    int f  = fm & 63;
    int t  = fm >> 6;
    int c  = ck / 9, kk = ck - 9 * c;
    float val = w[((t * Fdim + f) * Cdim + c) * Kdim + kk];
    __nv_bfloat16 hi = __float2bfloat16_rn(val);
    g_wA[0][idx] = hi;
    g_wA[1][idx] = __float2bfloat16_rn(val - __bfloat162float(hi));
}

__device__ __forceinline__ uint32_t smem_u32(const void* p) {
    uint32_t a;
    asm("{ .reg .u64 t; cvta.to.shared.u64 t, %1; cvt.u32.u64 %0, t; }" : "=r"(a) : "l"(p));
    return a;
}

#define LDSM_X4(r0,r1,r2,r3, addr) \
    asm volatile("ldmatrix.sync.aligned.m8n8.x4.shared.b16 {%0,%1,%2,%3}, [%4];" \
        : "=r"(r0),"=r"(r1),"=r"(r2),"=r"(r3) : "r"(addr))

#define LDSM_X4T(r0,r1,r2,r3, addr) \
    asm volatile("ldmatrix.sync.aligned.m8n8.x4.trans.shared.b16 {%0,%1,%2,%3}, [%4];" \
        : "=r"(r0),"=r"(r1),"=r"(r2),"=r"(r3) : "r"(addr))

#define MMA16816(c, a0,a1,a2,a3, b0,b1) \
    asm volatile("mma.sync.aligned.m16n8k16.row.col.f32.bf16.bf16.f32 " \
        "{%0,%1,%2,%3},{%4,%5,%6,%7},{%8,%9},{%0,%1,%2,%3};" \
        : "+f"((c)[0]),"+f"((c)[1]),"+f"((c)[2]),"+f"((c)[3]) \
        : "r"(a0),"r"(a1),"r"(a2),"r"(a3),"r"(b0),"r"(b1))

#define CP_ASYNC16(dst, src) \
    asm volatile("cp.async.ca.shared.global [%0], [%1], 16;" :: "r"(dst), "l"(src))

__global__ __launch_bounds__(256, 2)
void sepconv_mma_kernel(const float* __restrict__ x,
                        const float* __restrict__ coords,
                        const unsigned* __restrict__ sigma_p,
                        float* __restrict__ out)
{
    extern __shared__ __align__(16) unsigned char sm[];
    float* xs = (float*)(sm + OFF_XS);     // [32][136], halo
    float* ws = (float*)(sm + OFF_WS);     // [9][128]

    const int tid  = threadIdx.x;
    const int warp = tid >> 5;
    const int lane = tid & 31;
    const int bt   = blockIdx.y;
    const int t    = bt & (Tdim - 1);
    const int n0   = blockIdx.x * TILE_N;

    unsigned sb = *sigma_p;
    float sigma = (sb < 0x01000000u) ? (float)(int)sb : __uint_as_float(sb);
    float inv_sigma = 1.0f / sigma;

    // ---- stage x tile (halo, zero-padded) ----
    const float* xb = x + (size_t)bt * Cdim * Ndim;
    for (int idx = tid; idx < Cdim * 136; idx += 256) {
        int c = idx / 136, i = idx - c * 136;
        int m = n0 + i - 4;
        xs[idx] = (m >= 0 && m < Ndim) ? xb[c * Ndim + m] : 0.0f;
    }
    // ---- distance weights ws[k][n] ----
    const float* cb = coords + (size_t)bt * 3 * Ndim;
    for (int idx = tid; idx < Kdim * TILE_N; idx += 256) {
        int k = idx >> 7, n = idx & 127;
        int mc = n0 + n, mt2 = mc + k - 4;
        float cx = 0.f, cy = 0.f, cz = 0.f;
        if (mt2 >= 0 && mt2 < Ndim) { cx = cb[mt2]; cy = cb[Ndim + mt2]; cz = cb[2 * Ndim + mt2]; }
        float dx = cx - cb[mc], dy = cy - cb[Ndim + mc], dz = cz - cb[2 * Ndim + mc];
        float d2 = dx * dx + dy * dy + dz * dz;
        ws[k * 128 + n] = fmaxf(1.0f - sqrtf(d2) * inv_sigma, 0.0f);
    }
    __syncthreads();

    // warp tiling: 4 m16-tiles x 2 n64-halves
    const int mt = warp & 3;
    const int nh = warp >> 2;

    float acc[8][4];
    #pragma unroll
    for (int j = 0; j < 8; j++)
        #pragma unroll
        for (int q = 0; q < 4; q++) acc[j][q] = 0.0f;

    const uint32_t smb = smem_u32(sm);
    const int g = lane >> 3, rr = lane & 7;
    const uint32_t a_off = (uint32_t)((mt * 16 + (g & 1) * 8 + rr) * PA + (g >> 1) * 16);
    const uint32_t b_off = (uint32_t)(((g & 1) * 8 + rr) * PB + (nh * 64 + (g >> 1) * 8) * 2);

    // B-build thread mapping
    const int n2  = tid & 63;          // n pair
    const int ckr = tid >> 6;          // 0..3

    // A cp.async source/dst mapping (3 x 16B per thread)
    const int arow = tid / 6;                  // 0..42 per 256-slice pattern below
    (void)arow;

    for (int ch = 0; ch < NCH; ch++) {
        const int p = ch & 1;

        // ---- A chunk via cp.async (overlaps with B build) ----
        {
            const uint4* src0 = (const uint4*)g_wA[0] + ((size_t)t * Fdim) * 36 + ch * 6;
            const uint4* src1 = (const uint4*)g_wA[1] + ((size_t)t * Fdim) * 36 + ch * 6;
            #pragma unroll
            for (int it = 0; it < 3; it++) {
                int idx = it * 256 + tid;          // 0..767
                int h   = idx / 384;
                int rem = idx - h * 384;
                int row = rem / 6, col = rem - row * 6;
                uint32_t dst = smb + OFF_A + (uint32_t)((p * 2 + h) * ASZ + row * PA + col * 16);
                const uint4* src = (h ? src1 : src0) + (size_t)row * 36 + col;
                CP_ASYNC16(dst, src);
            }
            asm volatile("cp.async.commit_group;" ::: "memory");
        }
        // ---- build B chunk: hi (truncation) and lo (exact residual, rn) ----
        {
            unsigned* bh32 = (unsigned*)(sm + OFF_B + (p * 2) * BSZ);
            unsigned* bl32 = (unsigned*)(sm + OFF_B + (p * 2 + 1) * BSZ);
            #pragma unroll
            for (int cc = 0; cc < CHK; cc += 4) {
                int ccl = cc + ckr;
                int ck = ch * CHK + ccl;
                int c = ck / 9, k = ck - 9 * c;
                int nn = 2 * n2;
                float v0 = xs[c * 136 + nn + k]     * ws[k * 128 + nn];
                float v1 = xs[c * 136 + nn + 1 + k] * ws[k * 128 + nn + 1];
                unsigned u0 = __float_as_uint(v0), u1 = __float_as_uint(v1);
                // hi = truncate-to-bf16; pack both high halves with one PRMT
                unsigned hh;
                asm("prmt.b32 %0, %1, %2, 0x7632;" : "=r"(hh) : "r"(u0), "r"(u1));
                float r0 = v0 - __uint_as_float(u0 & 0xFFFF0000u);   // exact
                float r1 = v1 - __uint_as_float(u1 & 0xFFFF0000u);   // exact
                __nv_bfloat162 l2 = __floats2bfloat162_rn(r0, r1);
                bh32[ccl * (PB / 4) + n2] = hh;
                bl32[ccl * (PB / 4) + n2] = *(unsigned*)&l2;
            }
        }
        asm volatile("cp.async.wait_group 0;" ::: "memory");
        __syncthreads();   // single barrier per chunk (double-buffered)

        // ---- MMA phase: 3 k16-steps, fragments first, grouped products ----
        const uint32_t ah_base = smb + OFF_A + (p * 2) * ASZ + a_off;
        const uint32_t al_base = ah_base + ASZ;
        const uint32_t bh_base = smb + OFF_B + (p * 2) * BSZ + b_off;
        const uint32_t bl_base = bh_base + BSZ;
        #pragma unroll
        for (int ks = 0; ks < 3; ks++) {
            uint32_t ah[4], al[4], bh[4][4], bl[4][4];
            LDSM_X4(ah[0], ah[1], ah[2], ah[3], ah_base + ks * 32);
            LDSM_X4(al[0], al[1], al[2], al[3], al_base + ks * 32);
            #pragma unroll
            for (int bp = 0; bp < 4; bp++)
                LDSM_X4T(bh[bp][0], bh[bp][1], bh[bp][2], bh[bp][3],
                         bh_base + ks * 16 * PB + bp * 32);
            #pragma unroll
            for (int bp = 0; bp < 4; bp++)
                LDSM_X4T(bl[bp][0], bl[bp][1], bl[bp][2], bl[bp][3],
                         bl_base + ks * 16 * PB + bp * 32);
            // product 1: ah * bh
            #pragma unroll
            for (int bp = 0; bp < 4; bp++) {
                MMA16816(acc[bp*2],   ah[0], ah[1], ah[2], ah[3], bh[bp][0], bh[bp][1]);
                MMA16816(acc[bp*2+1], ah[0], ah[1], ah[2], ah[3], bh[bp][2], bh[bp][3]);
            }
            // product 2: ah * bl
            #pragma unroll
            for (int bp = 0; bp < 4; bp++) {
                MMA16816(acc[bp*2],   ah[0], ah[1], ah[2], ah[3], bl[bp][0], bl[bp][1]);
                MMA16816(acc[bp*2+1], ah[0], ah[1], ah[2], ah[3], bl[bp][2], bl[bp][3]);
            }
            // product 3: al * bh
            #pragma unroll
            for (int bp = 0; bp < 4; bp++) {
                MMA16816(acc[bp*2],   al[0], al[1], al[2], al[3], bh[bp][0], bh[bp][1]);
                MMA16816(acc[bp*2+1], al[0], al[1], al[2], al[3], bh[bp][2], bh[bp][3]);
            }
        }
        // no trailing barrier: next build targets the other parity buffers
    }

    // ---- epilogue: register fragments -> gmem ----
    float* ob = out + (size_t)bt * Fdim * Ndim;
    const int drow = lane >> 2;
    const int dcol = (lane & 3) * 2;
    #pragma unroll
    for (int j = 0; j < 8; j++) {
        int f  = mt * 16 + drow;
        int nc = n0 + nh * 64 + j * 8 + dcol;
        *(float2*)&ob[(size_t)f * Ndim + nc]       = make_float2(acc[j][0], acc[j][1]);
        *(float2*)&ob[(size_t)(f + 8) * Ndim + nc] = make_float2(acc[j][2], acc[j][3]);
    }
}

extern "C" void kernel_launch(void* const* d_in, const int* in_sizes, int n_in,
                              void* d_out, int out_size)
{
    const float*    x      = (const float*)d_in[0];
    const float*    coords = (const float*)d_in[1];
    const float*    w      = (const float*)d_in[2];
    const unsigned* sigma  = (const unsigned*)d_in[3];
    float*          out    = (float*)d_out;

    static int smem_set = 0;
    if (!smem_set) {
        cudaFuncSetAttribute(sepconv_mma_kernel,
                             cudaFuncAttributeMaxDynamicSharedMemorySize, SMEM_TOTAL);
        smem_set = 1;
    }

    prep_w<<<(Tdim * Fdim * CK + 255) / 256, 256>>>(w);

    dim3 grid(Ndim / TILE_N, Bdim * Tdim);
    sepconv_mma_kernel<<<grid, 256, SMEM_TOTAL>>>(x, coords, sigma, out);
}